// round 7
// baseline (speedup 1.0000x reference)
#include <cuda_runtime.h>
#include <math.h>

#define BSZ   2
#define CDIM  256
#define LDIM  4096
#define HEADS 8
#define HD    32
#define N3C   768

__device__ float g_q[BSZ*HEADS*LDIM*HD];
__device__ float g_k[BSZ*HEADS*LDIM*HD];
__device__ float g_v[BSZ*HEADS*LDIM*HD];
__device__ float g_o[BSZ*LDIM*CDIM];

__device__ __forceinline__ unsigned f2tf(float f) {
    unsigned r;
    asm("cvt.rna.tf32.f32 %0, %1;" : "=r"(r) : "f"(f));
    return r;
}

__device__ __forceinline__ void mma8(float* c, const unsigned* a, const unsigned* b) {
    asm volatile(
        "mma.sync.aligned.m16n8k8.row.col.f32.tf32.tf32.f32 "
        "{%0,%1,%2,%3},{%4,%5,%6,%7},{%8,%9},{%0,%1,%2,%3};"
        : "+f"(c[0]), "+f"(c[1]), "+f"(c[2]), "+f"(c[3])
        : "r"(a[0]), "r"(a[1]), "r"(a[2]), "r"(a[3]), "r"(b[0]), "r"(b[1]));
}

__device__ __forceinline__ void st_tf4(unsigned* dst, float4 v) {
    unsigned u[4] = {f2tf(v.x), f2tf(v.y), f2tf(v.z), f2tf(v.w)};
    *(uint4*)dst = *(uint4*)u;
}

__device__ __forceinline__ void cp16(void* s, const void* g) {
    unsigned sa = (unsigned)__cvta_generic_to_shared(s);
    asm volatile("cp.async.cg.shared.global [%0], [%1], 16;" :: "r"(sa), "l"(g));
}
__device__ __forceinline__ void cp_commit() {
    asm volatile("cp.async.commit_group;");
}
__device__ __forceinline__ void cp_wait0() {
    asm volatile("cp.async.wait_group 0;");
}

// ---------------------------------------------------------------------------
// Kernel 1: qkv via tf32 mma, operand-swapped; cp.async double buffer,
// one sync per K-chunk, cvt at fragment load.
// ---------------------------------------------------------------------------
__global__ void __launch_bounds__(256) qkv_gemm(const float* __restrict__ x,
                                                const float* __restrict__ w1,
                                                const float* __restrict__ b1) {
    __shared__ float WsF[2][32][72];   // [stage][k][n]  raw fp32
    __shared__ float XsF[2][32][72];   // [stage][k][m]

    const int b  = blockIdx.z;
    const int m0 = blockIdx.x * 64;
    const int n0 = blockIdx.y * 64;
    const int t  = threadIdx.x;
    const int lane = t & 31;
    const int warp = t >> 5;
    const int wr = warp >> 1;
    const int wc = warp & 1;
    const int g  = lane >> 2;
    const int tg = lane & 3;

    const float* xb = x + (size_t)b * CDIM * LDIM;
    float acc[4][4] = {};

    const int s_kk = t >> 4, s_c4 = (t & 15) * 4;
    const int s_kk2 = s_kk + 16;

    // prologue: chunk 0 -> buf 0
    cp16(&WsF[0][s_kk][s_c4],  &w1[(size_t)s_kk  * N3C + n0 + s_c4]);
    cp16(&WsF[0][s_kk2][s_c4], &w1[(size_t)s_kk2 * N3C + n0 + s_c4]);
    cp16(&XsF[0][s_kk][s_c4],  &xb[(size_t)s_kk  * LDIM + m0 + s_c4]);
    cp16(&XsF[0][s_kk2][s_c4], &xb[(size_t)s_kk2 * LDIM + m0 + s_c4]);
    cp_commit();

    #pragma unroll
    for (int i = 0; i < 8; i++) {
        const int cur = i & 1;
        cp_wait0();
        __syncthreads();
        if (i < 7) {
            const int nxt = 1 - cur;
            const int kn = (i + 1) * 32;
            cp16(&WsF[nxt][s_kk][s_c4],  &w1[(size_t)(kn + s_kk)  * N3C + n0 + s_c4]);
            cp16(&WsF[nxt][s_kk2][s_c4], &w1[(size_t)(kn + s_kk2) * N3C + n0 + s_c4]);
            cp16(&XsF[nxt][s_kk][s_c4],  &xb[(size_t)(kn + s_kk)  * LDIM + m0 + s_c4]);
            cp16(&XsF[nxt][s_kk2][s_c4], &xb[(size_t)(kn + s_kk2) * LDIM + m0 + s_c4]);
            cp_commit();
        }
        unsigned af[4][4];
        #pragma unroll
        for (int ks = 0; ks < 4; ks++) {
            af[ks][0] = f2tf(WsF[cur][ks * 8 + tg][wr * 16 + g]);
            af[ks][1] = f2tf(WsF[cur][ks * 8 + tg][wr * 16 + g + 8]);
            af[ks][2] = f2tf(WsF[cur][ks * 8 + tg + 4][wr * 16 + g]);
            af[ks][3] = f2tf(WsF[cur][ks * 8 + tg + 4][wr * 16 + g + 8]);
        }
        #pragma unroll
        for (int mb = 0; mb < 4; mb++) {
            int mc = wc * 32 + mb * 8 + g;
            #pragma unroll
            for (int ks = 0; ks < 4; ks++) {
                unsigned bf[2] = {f2tf(XsF[cur][ks * 8 + tg][mc]),
                                  f2tf(XsF[cur][ks * 8 + tg + 4][mc])};
                mma8(acc[mb], af[ks], bf);
            }
        }
    }

    // q gets 1/sqrt(hd) * log2(e) so attention can use exp2
    const float q_scale = 0.1767766952966368811f * 1.4426950408889634f;
    const int n_r0 = n0 + wr * 16 + g;
    const int n_r1 = n_r0 + 8;
    const int k3_0 = n_r0 % 3, h_0 = (n_r0 / 3) & 7, c_0 = n_r0 / 24;
    const int k3_1 = n_r1 % 3, h_1 = (n_r1 / 3) & 7, c_1 = n_r1 / 24;
    const float bias0 = b1[n_r0], bias1 = b1[n_r1];
    float* dst0 = (k3_0 == 0) ? g_q : (k3_0 == 1) ? g_k : g_v;
    float* dst1 = (k3_1 == 0) ? g_q : (k3_1 == 1) ? g_k : g_v;
    const float sc0 = (k3_0 == 0) ? q_scale : 1.f;
    const float sc1 = (k3_1 == 0) ? q_scale : 1.f;
    const size_t base0 = (size_t)(b * HEADS + h_0) * LDIM;
    const size_t base1 = (size_t)(b * HEADS + h_1) * LDIM;
    #pragma unroll
    for (int mb = 0; mb < 4; mb++) {
        int mA = m0 + wc * 32 + mb * 8 + 2 * tg;
        dst0[(base0 + mA)     * HD + c_0] = (acc[mb][0] + bias0) * sc0;
        dst0[(base0 + mA + 1) * HD + c_0] = (acc[mb][1] + bias0) * sc0;
        dst1[(base1 + mA)     * HD + c_1] = (acc[mb][2] + bias1) * sc1;
        dst1[(base1 + mA + 1) * HD + c_1] = (acc[mb][3] + bias1) * sc1;
    }
}

// ---------------------------------------------------------------------------
// Kernel 2: banded attention; cp.async double-buffered K/V, one sync per
// tile; S->P via intra-quad shuffles (no smem round trip); exp2.
// ---------------------------------------------------------------------------
__global__ void __launch_bounds__(256) attn_kernel() {
    __shared__ unsigned Qs[64][36];        // tf32 bits
    __shared__ float    KsF[2][64][36];    // raw fp32
    __shared__ float    VsF[2][64][40];
    __shared__ float    Red[64][33];
    __shared__ float    Lsm[64][2];

    const int qt = blockIdx.x;
    const int bh = blockIdx.y;
    const int i0 = qt * 64;
    const int t  = threadIdx.x;
    const int lane = t & 31;
    const int warp = t >> 5;
    const int wr = warp >> 1;
    const int wc = warp & 1;
    const int g  = lane >> 2;
    const int tg = lane & 3;

    const float* qb = g_q + (size_t)bh * LDIM * HD;
    const float* kb = g_k + (size_t)bh * LDIM * HD;
    const float* vb = g_v + (size_t)bh * LDIM * HD;

    const int s_row0 = t >> 3, s_c4 = (t & 7) * 4;
    const int s_row1 = s_row0 + 32;

    // stage Q once (tf32)
    st_tf4(&Qs[s_row0][s_c4], *(const float4*)&qb[(size_t)(i0 + s_row0) * HD + s_c4]);
    st_tf4(&Qs[s_row1][s_c4], *(const float4*)&qb[(size_t)(i0 + s_row1) * HD + s_c4]);

    const bool hasG = (qt == 0) || (qt == 63);
    const int  tlo  = max(0, i0 - 512) >> 6;
    const int  thi  = min(LDIM - 1, i0 + 63 + 512) >> 6;
    const int  lead  = (tlo > 0) ? 1 : 0;
    const int  trail = (thi < 63) ? 1 : 0;
    const int  nband = thi - tlo + 1;
    const int  cnt   = hasG ? 64 : (nband + lead + trail);

    const int t0 = hasG ? 0 : (lead ? 0 : tlo);
    {   // prologue: tile 0 -> buf 0
        const int j0 = t0 * 64;
        cp16(&KsF[0][s_row0][s_c4], &kb[(size_t)(j0 + s_row0) * HD + s_c4]);
        cp16(&KsF[0][s_row1][s_c4], &kb[(size_t)(j0 + s_row1) * HD + s_c4]);
        cp16(&VsF[0][s_row0][s_c4], &vb[(size_t)(j0 + s_row0) * HD + s_c4]);
        cp16(&VsF[0][s_row1][s_c4], &vb[(size_t)(j0 + s_row1) * HD + s_c4]);
        cp_commit();
    }
    __syncthreads();                       // Qs visible

    unsigned af[4][4];
    const int r0 = wr * 16 + g;
    const int r1 = r0 + 8;
    #pragma unroll
    for (int ks = 0; ks < 4; ks++) {
        af[ks][0] = Qs[r0][ks * 8 + tg];
        af[ks][1] = Qs[r1][ks * 8 + tg];
        af[ks][2] = Qs[r0][ks * 8 + tg + 4];
        af[ks][3] = Qs[r1][ks * 8 + tg + 4];
    }

    const int ir0 = i0 + r0, ir1 = i0 + r1;
    const bool ig0 = (ir0 == 0) || (ir0 == 63) || (ir0 == 4032) || (ir0 == 4095);
    const bool ig1 = (ir1 == 0) || (ir1 == 63) || (ir1 == 4032) || (ir1 == 4095);

    float oacc[4][4] = {};
    float ls0 = 0.f, ls1 = 0.f;
    int tcur = t0;
    const int shA = (lane & ~3) | (tg >> 1);
    const int shB = shA + 2;
    const bool odd = tg & 1;

    for (int it = 0; it < cnt; it++) {
        const int cur = it & 1;
        const int j0 = tcur * 64;

        cp_wait0();
        __syncthreads();                   // tile it ready; prev compute done
        if (it + 1 < cnt) {
            int nx = it + 1;
            int tnext;
            if (hasG) tnext = nx;
            else {
                int j = nx - lead;
                tnext = (nx == 0 && lead) ? 0 : ((j < nband) ? (tlo + j) : 63);
            }
            const int jn = tnext * 64;
            const int nxt = 1 - cur;
            cp16(&KsF[nxt][s_row0][s_c4], &kb[(size_t)(jn + s_row0) * HD + s_c4]);
            cp16(&KsF[nxt][s_row1][s_c4], &kb[(size_t)(jn + s_row1) * HD + s_c4]);
            cp16(&VsF[nxt][s_row0][s_c4], &vb[(size_t)(jn + s_row0) * HD + s_c4]);
            cp16(&VsF[nxt][s_row1][s_c4], &vb[(size_t)(jn + s_row1) * HD + s_c4]);
            cp_commit();
            tcur = tnext;
        }

        // S = Q @ K^T (warp: 16 rows x 32 keys)
        float sacc[4][4] = {};
        #pragma unroll
        for (int nb = 0; nb < 4; nb++) {
            int jn = wc * 32 + nb * 8 + g;
            #pragma unroll
            for (int ks = 0; ks < 4; ks++) {
                unsigned bf[2] = {f2tf(KsF[cur][jn][ks * 8 + tg]),
                                  f2tf(KsF[cur][jn][ks * 8 + tg + 4])};
                mma8(sacc[nb], af[ks], bf);
            }
        }

        // mask + exp2 + cvt, accumulate row sums
        unsigned pt[4][4];
        #pragma unroll
        for (int nb = 0; nb < 4; nb++) {
            int jb = j0 + wc * 32 + nb * 8 + 2 * tg;
            int jb1 = jb + 1;
            bool jg0 = (jb == 0) || (jb == 63) || (jb == 4032) || (jb == 4095);
            bool jg1 = (jb1 == 0) || (jb1 == 63) || (jb1 == 4032) || (jb1 == 4095);
            int d00 = ir0 - jb, d01 = ir0 - jb1, d10 = ir1 - jb, d11 = ir1 - jb1;
            float p0 = (ig0 || jg0 || (d00 <= 512 && d00 >= -512)) ? exp2f(sacc[nb][0]) : 0.f;
            float p1 = (ig0 || jg1 || (d01 <= 512 && d01 >= -512)) ? exp2f(sacc[nb][1]) : 0.f;
            float p2 = (ig1 || jg0 || (d10 <= 512 && d10 >= -512)) ? exp2f(sacc[nb][2]) : 0.f;
            float p3 = (ig1 || jg1 || (d11 <= 512 && d11 >= -512)) ? exp2f(sacc[nb][3]) : 0.f;
            pt[nb][0] = f2tf(p0); pt[nb][1] = f2tf(p1);
            pt[nb][2] = f2tf(p2); pt[nb][3] = f2tf(p3);
            ls0 += __uint_as_float(pt[nb][0]) + __uint_as_float(pt[nb][1]);
            ls1 += __uint_as_float(pt[nb][2]) + __uint_as_float(pt[nb][3]);
        }

        // PV over this warp's 32-key half, all 32 channels
        #pragma unroll
        for (int ks = 0; ks < 4; ks++) {
            unsigned e0 = __shfl_sync(~0u, pt[ks][0], shA);
            unsigned e1 = __shfl_sync(~0u, pt[ks][1], shA);
            unsigned e2 = __shfl_sync(~0u, pt[ks][2], shA);
            unsigned e3 = __shfl_sync(~0u, pt[ks][3], shA);
            unsigned f0 = __shfl_sync(~0u, pt[ks][0], shB);
            unsigned f1 = __shfl_sync(~0u, pt[ks][1], shB);
            unsigned f2v = __shfl_sync(~0u, pt[ks][2], shB);
            unsigned f3 = __shfl_sync(~0u, pt[ks][3], shB);
            unsigned pa[4];
            pa[0] = odd ? e1 : e0;
            pa[1] = odd ? e3 : e2;
            pa[2] = odd ? f1 : f0;
            pa[3] = odd ? f3 : f2v;
            const int vrow0 = wc * 32 + ks * 8 + tg;
            #pragma unroll
            for (int nb2 = 0; nb2 < 4; nb2++) {
                int cn = nb2 * 8 + g;
                unsigned vf[2] = {f2tf(VsF[cur][vrow0][cn]),
                                  f2tf(VsF[cur][vrow0 + 4][cn])};
                mma8(oacc[nb2], pa, vf);
            }
        }
    }

    ls0 += __shfl_xor_sync(~0u, ls0, 1); ls0 += __shfl_xor_sync(~0u, ls0, 2);
    ls1 += __shfl_xor_sync(~0u, ls1, 1); ls1 += __shfl_xor_sync(~0u, ls1, 2);
    if (tg == 0) { Lsm[r0][wc] = ls0; Lsm[r1][wc] = ls1; }
    if (wc == 1) {
        #pragma unroll
        for (int nb2 = 0; nb2 < 4; nb2++) {
            int c0 = nb2 * 8 + 2 * tg;
            Red[r0][c0] = oacc[nb2][0]; Red[r0][c0 + 1] = oacc[nb2][1];
            Red[r1][c0] = oacc[nb2][2]; Red[r1][c0 + 1] = oacc[nb2][3];
        }
    }
    __syncthreads();

    if (wc == 0) {
        float inv0 = 1.f / (Lsm[r0][0] + Lsm[r0][1]);
        float inv1 = 1.f / (Lsm[r1][0] + Lsm[r1][1]);
        const int b = bh >> 3, h = bh & 7;
        #pragma unroll
        for (int nb2 = 0; nb2 < 4; nb2++) {
            int c0 = nb2 * 8 + 2 * tg;
            float o0 = (oacc[nb2][0] + Red[r0][c0])     * inv0;
            float o1 = (oacc[nb2][1] + Red[r0][c0 + 1]) * inv0;
            float o2 = (oacc[nb2][2] + Red[r1][c0])     * inv1;
            float o3 = (oacc[nb2][3] + Red[r1][c0 + 1]) * inv1;
            g_o[((size_t)b * LDIM + ir0) * CDIM + c0 * 8 + h]       = o0;
            g_o[((size_t)b * LDIM + ir0) * CDIM + (c0 + 1) * 8 + h] = o1;
            g_o[((size_t)b * LDIM + ir1) * CDIM + c0 * 8 + h]       = o2;
            g_o[((size_t)b * LDIM + ir1) * CDIM + (c0 + 1) * 8 + h] = o3;
        }
    }
}

// ---------------------------------------------------------------------------
// Kernel 3: out via tf32 mma; cp.async double buffer, one sync per chunk.
// ---------------------------------------------------------------------------
__global__ void __launch_bounds__(256) out_gemm(const float* __restrict__ w2,
                                                const float* __restrict__ b2,
                                                float* __restrict__ out) {
    __shared__ float WsF[2][32][72];   // [stage][k][n]
    __shared__ float OsF[2][64][36];   // [stage][m][k]

    const int b  = blockIdx.z;
    const int m0 = blockIdx.x * 64;
    const int n0 = blockIdx.y * 64;
    const int t  = threadIdx.x;
    const int lane = t & 31;
    const int warp = t >> 5;
    const int wr = warp >> 1;
    const int wc = warp & 1;
    const int g  = lane >> 2;
    const int tg = lane & 3;

    const float* ob = g_o + (size_t)b * LDIM * CDIM;
    float acc[4][4] = {};

    const int w_kk = t >> 4, w_n4 = (t & 15) * 4;
    const int w_kk2 = w_kk + 16;
    const int o_mm = t >> 3, o_k4 = (t & 7) * 4;
    const int o_mm2 = o_mm + 32;

    cp16(&WsF[0][w_kk][w_n4],  &w2[(size_t)w_kk  * CDIM + n0 + w_n4]);
    cp16(&WsF[0][w_kk2][w_n4], &w2[(size_t)w_kk2 * CDIM + n0 + w_n4]);
    cp16(&OsF[0][o_mm][o_k4],  &ob[(size_t)(m0 + o_mm)  * CDIM + o_k4]);
    cp16(&OsF[0][o_mm2][o_k4], &ob[(size_t)(m0 + o_mm2) * CDIM + o_k4]);
    cp_commit();

    #pragma unroll
    for (int i = 0; i < 8; i++) {
        const int cur = i & 1;
        cp_wait0();
        __syncthreads();
        if (i < 7) {
            const int nxt = 1 - cur;
            const int kn = (i + 1) * 32;
            cp16(&WsF[nxt][w_kk][w_n4],  &w2[(size_t)(kn + w_kk)  * CDIM + n0 + w_n4]);
            cp16(&WsF[nxt][w_kk2][w_n4], &w2[(size_t)(kn + w_kk2) * CDIM + n0 + w_n4]);
            cp16(&OsF[nxt][o_mm][o_k4],  &ob[(size_t)(m0 + o_mm)  * CDIM + kn + o_k4]);
            cp16(&OsF[nxt][o_mm2][o_k4], &ob[(size_t)(m0 + o_mm2) * CDIM + kn + o_k4]);
            cp_commit();
        }
        unsigned af[4][4];
        #pragma unroll
        for (int ks = 0; ks < 4; ks++) {
            af[ks][0] = f2tf(WsF[cur][ks * 8 + tg][wr * 16 + g]);
            af[ks][1] = f2tf(WsF[cur][ks * 8 + tg][wr * 16 + g + 8]);
            af[ks][2] = f2tf(WsF[cur][ks * 8 + tg + 4][wr * 16 + g]);
            af[ks][3] = f2tf(WsF[cur][ks * 8 + tg + 4][wr * 16 + g + 8]);
        }
        #pragma unroll
        for (int mb = 0; mb < 4; mb++) {
            int mc = wc * 32 + mb * 8 + g;
            #pragma unroll
            for (int ks = 0; ks < 4; ks++) {
                unsigned bf[2] = {f2tf(OsF[cur][mc][ks * 8 + tg]),
                                  f2tf(OsF[cur][mc][ks * 8 + tg + 4])};
                mma8(acc[mb], af[ks], bf);
            }
        }
    }

    const int n_r0 = n0 + wr * 16 + g;
    const int n_r1 = n_r0 + 8;
    const float bias0 = b2[n_r0];
    const float bias1 = b2[n_r1];
    #pragma unroll
    for (int mb = 0; mb < 4; mb++) {
        int mA = m0 + wc * 32 + mb * 8 + 2 * tg;
        float2 v0 = {acc[mb][0] + bias0, acc[mb][1] + bias0};
        float2 v1 = {acc[mb][2] + bias1, acc[mb][3] + bias1};
        *(float2*)&out[((size_t)b * CDIM + n_r0) * LDIM + mA] = v0;
        *(float2*)&out[((size_t)b * CDIM + n_r1) * LDIM + mA] = v1;
    }
}

// ---------------------------------------------------------------------------
extern "C" void kernel_launch(void* const* d_in, const int* in_sizes, int n_in,
                              void* d_out, int out_size) {
    const float* x  = (const float*)d_in[0];
    const float* w1 = (const float*)d_in[1];
    const float* b1 = (const float*)d_in[2];
    const float* w2 = (const float*)d_in[3];
    const float* b2 = (const float*)d_in[4];
    float* out = (float*)d_out;

    qkv_gemm<<<dim3(LDIM / 64, N3C / 64, BSZ), 256>>>(x, w1, b1);
    attn_kernel<<<dim3(LDIM / 64, BSZ * HEADS), 256>>>();
    out_gemm<<<dim3(LDIM / 64, CDIM / 64, BSZ), 256>>>(w2, b2, out);
}

// round 8
// speedup vs baseline: 1.1917x; 1.1917x over previous
#include <cuda_runtime.h>
#include <math.h>

#define BSZ   2
#define CDIM  256
#define LDIM  4096
#define HEADS 8
#define HD    32
#define N3C   768

__device__ float g_q[BSZ*HEADS*LDIM*HD];
__device__ float g_k[BSZ*HEADS*LDIM*HD];
__device__ float g_v[BSZ*HEADS*LDIM*HD];
__device__ float g_o[BSZ*LDIM*CDIM];

__device__ __forceinline__ unsigned f2tf(float f) {
    unsigned r;
    asm("cvt.rna.tf32.f32 %0, %1;" : "=r"(r) : "f"(f));
    return r;
}

__device__ __forceinline__ void mma8(float* c, const unsigned* a, const unsigned* b) {
    asm volatile(
        "mma.sync.aligned.m16n8k8.row.col.f32.tf32.tf32.f32 "
        "{%0,%1,%2,%3},{%4,%5,%6,%7},{%8,%9},{%0,%1,%2,%3};"
        : "+f"(c[0]), "+f"(c[1]), "+f"(c[2]), "+f"(c[3])
        : "r"(a[0]), "r"(a[1]), "r"(a[2]), "r"(a[3]), "r"(b[0]), "r"(b[1]));
}

__device__ __forceinline__ void cp16(void* s, const void* g) {
    unsigned sa = (unsigned)__cvta_generic_to_shared(s);
    asm volatile("cp.async.cg.shared.global [%0], [%1], 16;" :: "r"(sa), "l"(g));
}
__device__ __forceinline__ void cp_commit() {
    asm volatile("cp.async.commit_group;");
}
__device__ __forceinline__ void cp_wait0() {
    asm volatile("cp.async.wait_group 0;");
}

// ---------------------------------------------------------------------------
// Kernel 1: qkv via tf32 mma, operand-swapped; cp.async double buffer.
// Epilogue stores q/k/v PRE-ROUNDED to tf32-representable fp32 so attention
// needs no conversions in its hot loop.
// ---------------------------------------------------------------------------
__global__ void __launch_bounds__(256) qkv_gemm(const float* __restrict__ x,
                                                const float* __restrict__ w1,
                                                const float* __restrict__ b1) {
    __shared__ float WsF[2][32][72];   // [stage][k][n]
    __shared__ float XsF[2][32][72];   // [stage][k][m]

    const int b  = blockIdx.z;
    const int m0 = blockIdx.x * 64;
    const int n0 = blockIdx.y * 64;
    const int t  = threadIdx.x;
    const int lane = t & 31;
    const int warp = t >> 5;
    const int wr = warp >> 1;
    const int wc = warp & 1;
    const int g  = lane >> 2;
    const int tg = lane & 3;

    const float* xb = x + (size_t)b * CDIM * LDIM;
    float acc[4][4] = {};

    const int s_kk = t >> 4, s_c4 = (t & 15) * 4;
    const int s_kk2 = s_kk + 16;

    cp16(&WsF[0][s_kk][s_c4],  &w1[(size_t)s_kk  * N3C + n0 + s_c4]);
    cp16(&WsF[0][s_kk2][s_c4], &w1[(size_t)s_kk2 * N3C + n0 + s_c4]);
    cp16(&XsF[0][s_kk][s_c4],  &xb[(size_t)s_kk  * LDIM + m0 + s_c4]);
    cp16(&XsF[0][s_kk2][s_c4], &xb[(size_t)s_kk2 * LDIM + m0 + s_c4]);
    cp_commit();

    #pragma unroll
    for (int i = 0; i < 8; i++) {
        const int cur = i & 1;
        cp_wait0();
        __syncthreads();
        if (i < 7) {
            const int nxt = 1 - cur;
            const int kn = (i + 1) * 32;
            cp16(&WsF[nxt][s_kk][s_c4],  &w1[(size_t)(kn + s_kk)  * N3C + n0 + s_c4]);
            cp16(&WsF[nxt][s_kk2][s_c4], &w1[(size_t)(kn + s_kk2) * N3C + n0 + s_c4]);
            cp16(&XsF[nxt][s_kk][s_c4],  &xb[(size_t)(kn + s_kk)  * LDIM + m0 + s_c4]);
            cp16(&XsF[nxt][s_kk2][s_c4], &xb[(size_t)(kn + s_kk2) * LDIM + m0 + s_c4]);
            cp_commit();
        }
        unsigned af[4][4];
        #pragma unroll
        for (int ks = 0; ks < 4; ks++) {
            af[ks][0] = f2tf(WsF[cur][ks * 8 + tg][wr * 16 + g]);
            af[ks][1] = f2tf(WsF[cur][ks * 8 + tg][wr * 16 + g + 8]);
            af[ks][2] = f2tf(WsF[cur][ks * 8 + tg + 4][wr * 16 + g]);
            af[ks][3] = f2tf(WsF[cur][ks * 8 + tg + 4][wr * 16 + g + 8]);
        }
        #pragma unroll
        for (int mb = 0; mb < 4; mb++) {
            int mc = wc * 32 + mb * 8 + g;
            #pragma unroll
            for (int ks = 0; ks < 4; ks++) {
                unsigned bf[2] = {f2tf(XsF[cur][ks * 8 + tg][mc]),
                                  f2tf(XsF[cur][ks * 8 + tg + 4][mc])};
                mma8(acc[mb], af[ks], bf);
            }
        }
    }

    // q gets 1/sqrt(hd) * log2(e) so attention uses exp2. All outputs are
    // rounded to tf32-representable fp32 here (rna), so attention feeds raw bits.
    const float q_scale = 0.1767766952966368811f * 1.4426950408889634f;
    const int n_r0 = n0 + wr * 16 + g;
    const int n_r1 = n_r0 + 8;
    const int k3_0 = n_r0 % 3, h_0 = (n_r0 / 3) & 7, c_0 = n_r0 / 24;
    const int k3_1 = n_r1 % 3, h_1 = (n_r1 / 3) & 7, c_1 = n_r1 / 24;
    const float bias0 = b1[n_r0], bias1 = b1[n_r1];
    float* dst0 = (k3_0 == 0) ? g_q : (k3_0 == 1) ? g_k : g_v;
    float* dst1 = (k3_1 == 0) ? g_q : (k3_1 == 1) ? g_k : g_v;
    const float sc0 = (k3_0 == 0) ? q_scale : 1.f;
    const float sc1 = (k3_1 == 0) ? q_scale : 1.f;
    const size_t base0 = (size_t)(b * HEADS + h_0) * LDIM;
    const size_t base1 = (size_t)(b * HEADS + h_1) * LDIM;
    #pragma unroll
    for (int mb = 0; mb < 4; mb++) {
        int mA = m0 + wc * 32 + mb * 8 + 2 * tg;
        dst0[(base0 + mA)     * HD + c_0] = __uint_as_float(f2tf((acc[mb][0] + bias0) * sc0));
        dst0[(base0 + mA + 1) * HD + c_0] = __uint_as_float(f2tf((acc[mb][1] + bias0) * sc0));
        dst1[(base1 + mA)     * HD + c_1] = __uint_as_float(f2tf((acc[mb][2] + bias1) * sc1));
        dst1[(base1 + mA + 1) * HD + c_1] = __uint_as_float(f2tf((acc[mb][3] + bias1) * sc1));
    }
}

// ---------------------------------------------------------------------------
// Kernel 2: banded attention. q/k/v are pre-rounded tf32 values: raw bits go
// straight to mma (zero cvts for Q/K/V). Interior band tiles skip masking.
// Global tokens handled in a small zero-padded epilogue (non-hasG blocks).
// ---------------------------------------------------------------------------
__global__ void __launch_bounds__(256) attn_kernel() {
    __shared__ float QsF[64][36];
    __shared__ float KsF[2][64][36];
    __shared__ float VsF[2][64][40];
    __shared__ float GsK[8][36];
    __shared__ float GsV[8][40];
    __shared__ float Red[64][33];
    __shared__ float Lsm[64][2];

    const int qt = blockIdx.x;
    const int bh = blockIdx.y;
    const int i0 = qt * 64;
    const int t  = threadIdx.x;
    const int lane = t & 31;
    const int warp = t >> 5;
    const int wr = warp >> 1;
    const int wc = warp & 1;
    const int g  = lane >> 2;
    const int tg = lane & 3;

    const float* qb = g_q + (size_t)bh * LDIM * HD;
    const float* kb = g_k + (size_t)bh * LDIM * HD;
    const float* vb = g_v + (size_t)bh * LDIM * HD;

    const int s_row0 = t >> 3, s_c4 = (t & 7) * 4;
    const int s_row1 = s_row0 + 32;

    const bool hasG = (qt == 0) || (qt == 63);
    const int  tlo  = max(0, i0 - 512) >> 6;
    const int  thi  = min(LDIM - 1, i0 + 63 + 512) >> 6;
    const int  cnt  = hasG ? 64 : (thi - tlo + 1);
    const int  t0   = hasG ? 0 : tlo;

    // stage Q (async) + global-token tiles (sync, once)
    cp16(&QsF[s_row0][s_c4], &qb[(size_t)(i0 + s_row0) * HD + s_c4]);
    cp16(&QsF[s_row1][s_c4], &qb[(size_t)(i0 + s_row1) * HD + s_c4]);
    if (!hasG) {
        if (t < 64) {
            int q2 = t & 31;
            int row = q2 >> 3, c4 = (q2 & 7) * 4;
            int jr = (row == 0) ? 0 : (row == 1) ? 63 : (row == 2) ? 4032 : 4095;
            if (t < 32) *(float4*)&GsK[row][c4] = *(const float4*)&kb[(size_t)jr * HD + c4];
            else        *(float4*)&GsV[row][c4] = *(const float4*)&vb[(size_t)jr * HD + c4];
        } else if (t < 128) {
            int q2 = (t - 64) & 31;
            int row = 4 + (q2 >> 3), c4 = (q2 & 7) * 4;
            float4 z = {0.f, 0.f, 0.f, 0.f};
            if (t < 96) *(float4*)&GsK[row][c4] = z;
            else        *(float4*)&GsV[row][c4] = z;
        }
    }
    {   // prologue: first K/V tile -> buf 0
        const int j0 = t0 * 64;
        cp16(&KsF[0][s_row0][s_c4], &kb[(size_t)(j0 + s_row0) * HD + s_c4]);
        cp16(&KsF[0][s_row1][s_c4], &kb[(size_t)(j0 + s_row1) * HD + s_c4]);
        cp16(&VsF[0][s_row0][s_c4], &vb[(size_t)(j0 + s_row0) * HD + s_c4]);
        cp16(&VsF[0][s_row1][s_c4], &vb[(size_t)(j0 + s_row1) * HD + s_c4]);
        cp_commit();
    }
    cp_wait0();
    __syncthreads();

    unsigned af[4][4];
    const int r0 = wr * 16 + g;
    const int r1 = r0 + 8;
    #pragma unroll
    for (int ks = 0; ks < 4; ks++) {
        af[ks][0] = __float_as_uint(QsF[r0][ks * 8 + tg]);
        af[ks][1] = __float_as_uint(QsF[r1][ks * 8 + tg]);
        af[ks][2] = __float_as_uint(QsF[r0][ks * 8 + tg + 4]);
        af[ks][3] = __float_as_uint(QsF[r1][ks * 8 + tg + 4]);
    }

    const int ir0 = i0 + r0, ir1 = i0 + r1;
    const bool ig0 = (ir0 == 0) || (ir0 == 63) || (ir0 == 4032) || (ir0 == 4095);
    const bool ig1 = (ir1 == 0) || (ir1 == 63) || (ir1 == 4032) || (ir1 == 4095);

    float oacc[4][4] = {};
    float ls0 = 0.f, ls1 = 0.f;
    int tcur = t0;
    const int shA = (lane & ~3) | (tg >> 1);
    const int shB = shA + 2;
    const bool odd = tg & 1;

    for (int it = 0; it < cnt; it++) {
        const int cur = it & 1;
        const int tcomp = tcur;
        const int j0 = tcomp * 64;

        cp_wait0();
        __syncthreads();
        if (it + 1 < cnt) {
            const int tnext = hasG ? (it + 1) : (tlo + it + 1);
            const int jn = tnext * 64;
            const int nxt = 1 - cur;
            cp16(&KsF[nxt][s_row0][s_c4], &kb[(size_t)(jn + s_row0) * HD + s_c4]);
            cp16(&KsF[nxt][s_row1][s_c4], &kb[(size_t)(jn + s_row1) * HD + s_c4]);
            cp16(&VsF[nxt][s_row0][s_c4], &vb[(size_t)(jn + s_row0) * HD + s_c4]);
            cp16(&VsF[nxt][s_row1][s_c4], &vb[(size_t)(jn + s_row1) * HD + s_c4]);
            cp_commit();
            tcur = tnext;
        }

        // S = Q @ K^T (raw bits: values pre-rounded to tf32)
        float sacc[4][4] = {};
        #pragma unroll
        for (int nb = 0; nb < 4; nb++) {
            int jn = wc * 32 + nb * 8 + g;
            #pragma unroll
            for (int ks = 0; ks < 4; ks++) {
                unsigned bf[2] = {__float_as_uint(KsF[cur][jn][ks * 8 + tg]),
                                  __float_as_uint(KsF[cur][jn][ks * 8 + tg + 4])};
                mma8(sacc[nb], af[ks], bf);
            }
        }

        // exp2 (+ mask only on edge tiles / hasG blocks)
        unsigned pt[4][4];
        const bool mtile = hasG || (tcomp == tlo) || (tcomp == thi);
        if (!mtile) {
            #pragma unroll
            for (int nb = 0; nb < 4; nb++) {
                pt[nb][0] = f2tf(exp2f(sacc[nb][0]));
                pt[nb][1] = f2tf(exp2f(sacc[nb][1]));
                pt[nb][2] = f2tf(exp2f(sacc[nb][2]));
                pt[nb][3] = f2tf(exp2f(sacc[nb][3]));
                ls0 += __uint_as_float(pt[nb][0]) + __uint_as_float(pt[nb][1]);
                ls1 += __uint_as_float(pt[nb][2]) + __uint_as_float(pt[nb][3]);
            }
        } else {
            #pragma unroll
            for (int nb = 0; nb < 4; nb++) {
                int jb = j0 + wc * 32 + nb * 8 + 2 * tg;
                int jb1 = jb + 1;
                bool jg0 = (jb == 0) || (jb == 63) || (jb == 4032) || (jb == 4095);
                bool jg1 = (jb1 == 0) || (jb1 == 63) || (jb1 == 4032) || (jb1 == 4095);
                int d00 = ir0 - jb, d01 = ir0 - jb1, d10 = ir1 - jb, d11 = ir1 - jb1;
                float p0 = (ig0 || jg0 || (d00 <= 512 && d00 >= -512)) ? exp2f(sacc[nb][0]) : 0.f;
                float p1 = (ig0 || jg1 || (d01 <= 512 && d01 >= -512)) ? exp2f(sacc[nb][1]) : 0.f;
                float p2 = (ig1 || jg0 || (d10 <= 512 && d10 >= -512)) ? exp2f(sacc[nb][2]) : 0.f;
                float p3 = (ig1 || jg1 || (d11 <= 512 && d11 >= -512)) ? exp2f(sacc[nb][3]) : 0.f;
                pt[nb][0] = f2tf(p0); pt[nb][1] = f2tf(p1);
                pt[nb][2] = f2tf(p2); pt[nb][3] = f2tf(p3);
                ls0 += __uint_as_float(pt[nb][0]) + __uint_as_float(pt[nb][1]);
                ls1 += __uint_as_float(pt[nb][2]) + __uint_as_float(pt[nb][3]);
            }
        }

        // PV over this warp's 32-key half
        #pragma unroll
        for (int ks = 0; ks < 4; ks++) {
            unsigned e0 = __shfl_sync(~0u, pt[ks][0], shA);
            unsigned e1 = __shfl_sync(~0u, pt[ks][1], shA);
            unsigned e2 = __shfl_sync(~0u, pt[ks][2], shA);
            unsigned e3 = __shfl_sync(~0u, pt[ks][3], shA);
            unsigned f0 = __shfl_sync(~0u, pt[ks][0], shB);
            unsigned f1 = __shfl_sync(~0u, pt[ks][1], shB);
            unsigned f2v = __shfl_sync(~0u, pt[ks][2], shB);
            unsigned f3 = __shfl_sync(~0u, pt[ks][3], shB);
            unsigned pa[4];
            pa[0] = odd ? e1 : e0;
            pa[1] = odd ? e3 : e2;
            pa[2] = odd ? f1 : f0;
            pa[3] = odd ? f3 : f2v;
            const int vrow0 = wc * 32 + ks * 8 + tg;
            #pragma unroll
            for (int nb2 = 0; nb2 < 4; nb2++) {
                int cn = nb2 * 8 + g;
                unsigned vf[2] = {__float_as_uint(VsF[cur][vrow0][cn]),
                                  __float_as_uint(VsF[cur][vrow0 + 4][cn])};
                mma8(oacc[nb2], pa, vf);
            }
        }
    }

    // Global-token epilogue (non-hasG blocks; wc==0 warps only, zero-padded 8 keys)
    if (!hasG && wc == 0) {
        float sg[4] = {};
        #pragma unroll
        for (int ks = 0; ks < 4; ks++) {
            unsigned bg[2] = {__float_as_uint(GsK[g][ks * 8 + tg]),
                              __float_as_uint(GsK[g][ks * 8 + tg + 4])};
            mma8(sg, af[ks], bg);
        }
        const bool leadOK  = (tlo > 0);
        const bool trailOK = (thi < 63);
        const int c0i = 2 * tg, c1i = 2 * tg + 1;
        const bool v0 = (c0i < 2) ? leadOK : (c0i < 4 ? trailOK : false);
        const bool v1 = (c1i < 2) ? leadOK : (c1i < 4 ? trailOK : false);
        unsigned ptg[4];
        ptg[0] = f2tf(v0 ? exp2f(sg[0]) : 0.f);
        ptg[1] = f2tf(v1 ? exp2f(sg[1]) : 0.f);
        ptg[2] = f2tf(v0 ? exp2f(sg[2]) : 0.f);
        ptg[3] = f2tf(v1 ? exp2f(sg[3]) : 0.f);
        ls0 += __uint_as_float(ptg[0]) + __uint_as_float(ptg[1]);
        ls1 += __uint_as_float(ptg[2]) + __uint_as_float(ptg[3]);
        unsigned e0 = __shfl_sync(~0u, ptg[0], shA);
        unsigned e1 = __shfl_sync(~0u, ptg[1], shA);
        unsigned e2 = __shfl_sync(~0u, ptg[2], shA);
        unsigned e3 = __shfl_sync(~0u, ptg[3], shA);
        unsigned f0 = __shfl_sync(~0u, ptg[0], shB);
        unsigned f1 = __shfl_sync(~0u, ptg[1], shB);
        unsigned f2v = __shfl_sync(~0u, ptg[2], shB);
        unsigned f3 = __shfl_sync(~0u, ptg[3], shB);
        unsigned pa[4];
        pa[0] = odd ? e1 : e0;
        pa[1] = odd ? e3 : e2;
        pa[2] = odd ? f1 : f0;
        pa[3] = odd ? f3 : f2v;
        #pragma unroll
        for (int nb2 = 0; nb2 < 4; nb2++) {
            int cn = nb2 * 8 + g;
            unsigned vf[2] = {__float_as_uint(GsV[tg][cn]),
                              __float_as_uint(GsV[tg + 4][cn])};
            mma8(oacc[nb2], pa, vf);
        }
    }

    ls0 += __shfl_xor_sync(~0u, ls0, 1); ls0 += __shfl_xor_sync(~0u, ls0, 2);
    ls1 += __shfl_xor_sync(~0u, ls1, 1); ls1 += __shfl_xor_sync(~0u, ls1, 2);
    if (tg == 0) { Lsm[r0][wc] = ls0; Lsm[r1][wc] = ls1; }
    if (wc == 1) {
        #pragma unroll
        for (int nb2 = 0; nb2 < 4; nb2++) {
            int c0 = nb2 * 8 + 2 * tg;
            Red[r0][c0] = oacc[nb2][0]; Red[r0][c0 + 1] = oacc[nb2][1];
            Red[r1][c0] = oacc[nb2][2]; Red[r1][c0 + 1] = oacc[nb2][3];
        }
    }
    __syncthreads();

    if (wc == 0) {
        float inv0 = 1.f / (Lsm[r0][0] + Lsm[r0][1]);
        float inv1 = 1.f / (Lsm[r1][0] + Lsm[r1][1]);
        const int b = bh >> 3, h = bh & 7;
        #pragma unroll
        for (int nb2 = 0; nb2 < 4; nb2++) {
            int c0 = nb2 * 8 + 2 * tg;
            float o0 = (oacc[nb2][0] + Red[r0][c0])     * inv0;
            float o1 = (oacc[nb2][1] + Red[r0][c0 + 1]) * inv0;
            float o2 = (oacc[nb2][2] + Red[r1][c0])     * inv1;
            float o3 = (oacc[nb2][3] + Red[r1][c0 + 1]) * inv1;
            g_o[((size_t)b * LDIM + ir0) * CDIM + c0 * 8 + h]       = o0;
            g_o[((size_t)b * LDIM + ir0) * CDIM + (c0 + 1) * 8 + h] = o1;
            g_o[((size_t)b * LDIM + ir1) * CDIM + c0 * 8 + h]       = o2;
            g_o[((size_t)b * LDIM + ir1) * CDIM + (c0 + 1) * 8 + h] = o3;
        }
    }
}

// ---------------------------------------------------------------------------
// Kernel 3: out via tf32 mma; cp.async double buffer. (unchanged)
// ---------------------------------------------------------------------------
__global__ void __launch_bounds__(256) out_gemm(const float* __restrict__ w2,
                                                const float* __restrict__ b2,
                                                float* __restrict__ out) {
    __shared__ float WsF[2][32][72];
    __shared__ float OsF[2][64][36];

    const int b  = blockIdx.z;
    const int m0 = blockIdx.x * 64;
    const int n0 = blockIdx.y * 64;
    const int t  = threadIdx.x;
    const int lane = t & 31;
    const int warp = t >> 5;
    const int wr = warp >> 1;
    const int wc = warp & 1;
    const int g  = lane >> 2;
    const int tg = lane & 3;

    const float* ob = g_o + (size_t)b * LDIM * CDIM;
    float acc[4][4] = {};

    const int w_kk = t >> 4, w_n4 = (t & 15) * 4;
    const int w_kk2 = w_kk + 16;
    const int o_mm = t >> 3, o_k4 = (t & 7) * 4;
    const int o_mm2 = o_mm + 32;

    cp16(&WsF[0][w_kk][w_n4],  &w2[(size_t)w_kk  * CDIM + n0 + w_n4]);
    cp16(&WsF[0][w_kk2][w_n4], &w2[(size_t)w_kk2 * CDIM + n0 + w_n4]);
    cp16(&OsF[0][o_mm][o_k4],  &ob[(size_t)(m0 + o_mm)  * CDIM + o_k4]);
    cp16(&OsF[0][o_mm2][o_k4], &ob[(size_t)(m0 + o_mm2) * CDIM + o_k4]);
    cp_commit();

    #pragma unroll
    for (int i = 0; i < 8; i++) {
        const int cur = i & 1;
        cp_wait0();
        __syncthreads();
        if (i < 7) {
            const int nxt = 1 - cur;
            const int kn = (i + 1) * 32;
            cp16(&WsF[nxt][w_kk][w_n4],  &w2[(size_t)(kn + w_kk)  * CDIM + n0 + w_n4]);
            cp16(&WsF[nxt][w_kk2][w_n4], &w2[(size_t)(kn + w_kk2) * CDIM + n0 + w_n4]);
            cp16(&OsF[nxt][o_mm][o_k4],  &ob[(size_t)(m0 + o_mm)  * CDIM + kn + o_k4]);
            cp16(&OsF[nxt][o_mm2][o_k4], &ob[(size_t)(m0 + o_mm2) * CDIM + kn + o_k4]);
            cp_commit();
        }
        unsigned af[4][4];
        #pragma unroll
        for (int ks = 0; ks < 4; ks++) {
            af[ks][0] = f2tf(WsF[cur][ks * 8 + tg][wr * 16 + g]);
            af[ks][1] = f2tf(WsF[cur][ks * 8 + tg][wr * 16 + g + 8]);
            af[ks][2] = f2tf(WsF[cur][ks * 8 + tg + 4][wr * 16 + g]);
            af[ks][3] = f2tf(WsF[cur][ks * 8 + tg + 4][wr * 16 + g + 8]);
        }
        #pragma unroll
        for (int mb = 0; mb < 4; mb++) {
            int mc = wc * 32 + mb * 8 + g;
            #pragma unroll
            for (int ks = 0; ks < 4; ks++) {
                unsigned bf[2] = {f2tf(OsF[cur][mc][ks * 8 + tg]),
                                  f2tf(OsF[cur][mc][ks * 8 + tg + 4])};
                mma8(acc[mb], af[ks], bf);
            }
        }
    }

    const int n_r0 = n0 + wr * 16 + g;
    const int n_r1 = n_r0 + 8;
    const float bias0 = b2[n_r0];
    const float bias1 = b2[n_r1];
    #pragma unroll
    for (int mb = 0; mb < 4; mb++) {
        int mA = m0 + wc * 32 + mb * 8 + 2 * tg;
        float2 v0 = {acc[mb][0] + bias0, acc[mb][1] + bias0};
        float2 v1 = {acc[mb][2] + bias1, acc[mb][3] + bias1};
        *(float2*)&out[((size_t)b * CDIM + n_r0) * LDIM + mA] = v0;
        *(float2*)&out[((size_t)b * CDIM + n_r1) * LDIM + mA] = v1;
    }
}

// ---------------------------------------------------------------------------
extern "C" void kernel_launch(void* const* d_in, const int* in_sizes, int n_in,
                              void* d_out, int out_size) {
    const float* x  = (const float*)d_in[0];
    const float* w1 = (const float*)d_in[1];
    const float* b1 = (const float*)d_in[2];
    const float* w2 = (const float*)d_in[3];
    const float* b2 = (const float*)d_in[4];
    float* out = (float*)d_out;

    qkv_gemm<<<dim3(LDIM / 64, N3C / 64, BSZ), 256>>>(x, w1, b1);
    attn_kernel<<<dim3(LDIM / 64, BSZ * HEADS), 256>>>();
    out_gemm<<<dim3(LDIM / 64, CDIM / 64, BSZ), 256>>>(w2, b2, out);
}

// round 9
// speedup vs baseline: 1.5775x; 1.3237x over previous
#include <cuda_runtime.h>
#include <cuda_fp16.h>
#include <math.h>

#define BSZ   2
#define CDIM  256
#define LDIM  4096
#define HEADS 8
#define HD    32
#define N3C   768

// q,k: [bh][L][32] halves;  v: [bh][c][L] halves (channel-major for PV B-frags)
__device__ __half g_q[BSZ*HEADS*LDIM*HD];
__device__ __half g_k[BSZ*HEADS*LDIM*HD];
__device__ __half g_v[BSZ*HEADS*LDIM*HD];
__device__ float  g_o[BSZ*LDIM*CDIM];

__device__ __forceinline__ unsigned f2tf(float f) {
    unsigned r;
    asm("cvt.rna.tf32.f32 %0, %1;" : "=r"(r) : "f"(f));
    return r;
}

// tf32 m16n8k8 (GEMM kernels)
__device__ __forceinline__ void mma8(float* c, const unsigned* a, const unsigned* b) {
    asm volatile(
        "mma.sync.aligned.m16n8k8.row.col.f32.tf32.tf32.f32 "
        "{%0,%1,%2,%3},{%4,%5,%6,%7},{%8,%9},{%0,%1,%2,%3};"
        : "+f"(c[0]), "+f"(c[1]), "+f"(c[2]), "+f"(c[3])
        : "r"(a[0]), "r"(a[1]), "r"(a[2]), "r"(a[3]), "r"(b[0]), "r"(b[1]));
}

// fp16 m16n8k16 (attention)
__device__ __forceinline__ void mma16(float* c, const unsigned* a, const unsigned* b) {
    asm volatile(
        "mma.sync.aligned.m16n8k16.row.col.f32.f16.f16.f32 "
        "{%0,%1,%2,%3},{%4,%5,%6,%7},{%8,%9},{%0,%1,%2,%3};"
        : "+f"(c[0]), "+f"(c[1]), "+f"(c[2]), "+f"(c[3])
        : "r"(a[0]), "r"(a[1]), "r"(a[2]), "r"(a[3]), "r"(b[0]), "r"(b[1]));
}

// pack two fp32 -> f16x2 (lo -> low half)
__device__ __forceinline__ unsigned pk2(float lo, float hi) {
    unsigned r;
    asm("cvt.rn.f16x2.f32 %0, %1, %2;" : "=r"(r) : "f"(hi), "f"(lo));
    return r;
}

__device__ __forceinline__ void cp16(void* s, const void* g) {
    unsigned sa = (unsigned)__cvta_generic_to_shared(s);
    asm volatile("cp.async.cg.shared.global [%0], [%1], 16;" :: "r"(sa), "l"(g));
}
__device__ __forceinline__ void cp_commit() {
    asm volatile("cp.async.commit_group;");
}
__device__ __forceinline__ void cp_wait0() {
    asm volatile("cp.async.wait_group 0;");
}

// ---------------------------------------------------------------------------
// Kernel 1: qkv via tf32 mma (unchanged math); epilogue emits fp16 q/k/v.
// ---------------------------------------------------------------------------
__global__ void __launch_bounds__(256) qkv_gemm(const float* __restrict__ x,
                                                const float* __restrict__ w1,
                                                const float* __restrict__ b1) {
    __shared__ float WsF[2][32][72];
    __shared__ float XsF[2][32][72];

    const int b  = blockIdx.z;
    const int m0 = blockIdx.x * 64;
    const int n0 = blockIdx.y * 64;
    const int t  = threadIdx.x;
    const int lane = t & 31;
    const int warp = t >> 5;
    const int wr = warp >> 1;
    const int wc = warp & 1;
    const int g  = lane >> 2;
    const int tg = lane & 3;

    const float* xb = x + (size_t)b * CDIM * LDIM;
    float acc[4][4] = {};

    const int s_kk = t >> 4, s_c4 = (t & 15) * 4;
    const int s_kk2 = s_kk + 16;

    cp16(&WsF[0][s_kk][s_c4],  &w1[(size_t)s_kk  * N3C + n0 + s_c4]);
    cp16(&WsF[0][s_kk2][s_c4], &w1[(size_t)s_kk2 * N3C + n0 + s_c4]);
    cp16(&XsF[0][s_kk][s_c4],  &xb[(size_t)s_kk  * LDIM + m0 + s_c4]);
    cp16(&XsF[0][s_kk2][s_c4], &xb[(size_t)s_kk2 * LDIM + m0 + s_c4]);
    cp_commit();

    #pragma unroll
    for (int i = 0; i < 8; i++) {
        const int cur = i & 1;
        cp_wait0();
        __syncthreads();
        if (i < 7) {
            const int nxt = 1 - cur;
            const int kn = (i + 1) * 32;
            cp16(&WsF[nxt][s_kk][s_c4],  &w1[(size_t)(kn + s_kk)  * N3C + n0 + s_c4]);
            cp16(&WsF[nxt][s_kk2][s_c4], &w1[(size_t)(kn + s_kk2) * N3C + n0 + s_c4]);
            cp16(&XsF[nxt][s_kk][s_c4],  &xb[(size_t)(kn + s_kk)  * LDIM + m0 + s_c4]);
            cp16(&XsF[nxt][s_kk2][s_c4], &xb[(size_t)(kn + s_kk2) * LDIM + m0 + s_c4]);
            cp_commit();
        }
        unsigned af[4][4];
        #pragma unroll
        for (int ks = 0; ks < 4; ks++) {
            af[ks][0] = f2tf(WsF[cur][ks * 8 + tg][wr * 16 + g]);
            af[ks][1] = f2tf(WsF[cur][ks * 8 + tg][wr * 16 + g + 8]);
            af[ks][2] = f2tf(WsF[cur][ks * 8 + tg + 4][wr * 16 + g]);
            af[ks][3] = f2tf(WsF[cur][ks * 8 + tg + 4][wr * 16 + g + 8]);
        }
        #pragma unroll
        for (int mb = 0; mb < 4; mb++) {
            int mc = wc * 32 + mb * 8 + g;
            #pragma unroll
            for (int ks = 0; ks < 4; ks++) {
                unsigned bf[2] = {f2tf(XsF[cur][ks * 8 + tg][mc]),
                                  f2tf(XsF[cur][ks * 8 + tg + 4][mc])};
                mma8(acc[mb], af[ks], bf);
            }
        }
    }

    // q gets 1/sqrt(hd)*log2(e) so attention uses exp2; outputs stored fp16.
    const float q_scale = 0.1767766952966368811f * 1.4426950408889634f;
    const int n_r0 = n0 + wr * 16 + g;
    const int n_r1 = n_r0 + 8;
    const int k3_0 = n_r0 % 3, h_0 = (n_r0 / 3) & 7, c_0 = n_r0 / 24;
    const int k3_1 = n_r1 % 3, h_1 = (n_r1 / 3) & 7, c_1 = n_r1 / 24;
    const float bias0 = b1[n_r0], bias1 = b1[n_r1];
    const float sc0 = (k3_0 == 0) ? q_scale : 1.f;
    const float sc1 = (k3_1 == 0) ? q_scale : 1.f;
    const int bh0 = b * HEADS + h_0, bh1 = b * HEADS + h_1;

    #pragma unroll
    for (int mb = 0; mb < 4; mb++) {
        int mA = m0 + wc * 32 + mb * 8 + 2 * tg;
        float v00 = (acc[mb][0] + bias0) * sc0, v01 = (acc[mb][1] + bias0) * sc0;
        float v10 = (acc[mb][2] + bias1) * sc1, v11 = (acc[mb][3] + bias1) * sc1;
        if (k3_0 == 2) {
            *(__half2*)&g_v[((size_t)bh0 * HD + c_0) * LDIM + mA] = __floats2half2_rn(v00, v01);
        } else {
            __half* d = (k3_0 == 0) ? g_q : g_k;
            d[((size_t)bh0 * LDIM + mA)     * HD + c_0] = __float2half_rn(v00);
            d[((size_t)bh0 * LDIM + mA + 1) * HD + c_0] = __float2half_rn(v01);
        }
        if (k3_1 == 2) {
            *(__half2*)&g_v[((size_t)bh1 * HD + c_1) * LDIM + mA] = __floats2half2_rn(v10, v11);
        } else {
            __half* d = (k3_1 == 0) ? g_q : g_k;
            d[((size_t)bh1 * LDIM + mA)     * HD + c_1] = __float2half_rn(v10);
            d[((size_t)bh1 * LDIM + mA + 1) * HD + c_1] = __float2half_rn(v11);
        }
    }
}

// ---------------------------------------------------------------------------
// Kernel 2: banded attention, fp16 m16n8k16. S accumulator packs directly
// into PV A-fragments (no shuffles, no smem P). V is channel-major so PV
// B-frags are contiguous half2. cp.async double buffer, 2 syncs/tile.
// ---------------------------------------------------------------------------
__global__ void __launch_bounds__(256) attn_kernel() {
    __shared__ __half Qs[64][40];
    __shared__ __half Ks[2][64][40];
    __shared__ __half Vt[2][32][72];     // [c][j]
    __shared__ __half GsK[8][40];        // rows 0..3 = global keys, 4..7 zero
    __shared__ __half Vgt[32][12];       // [c][j] globals, j>=4 zero
    __shared__ float  Red[64][33];
    __shared__ float  Lsm[64][2];

    const int qt = blockIdx.x;
    const int bh = blockIdx.y;
    const int i0 = qt * 64;
    const int t  = threadIdx.x;
    const int lane = t & 31;
    const int warp = t >> 5;
    const int wr = warp >> 1;
    const int wc = warp & 1;
    const int g  = lane >> 2;
    const int tg = lane & 3;

    const __half* qb  = g_q + (size_t)bh * LDIM * HD;
    const __half* kb  = g_k + (size_t)bh * LDIM * HD;
    const __half* vbt = g_v + (size_t)bh * HD * LDIM;   // [c][L]

    const int k_row = t >> 2, k_seg = t & 3;   // K/Q staging: 64 rows x 4 segs
    const int v_c   = t >> 3, v_seg = t & 7;   // Vt staging: 32 rows x 8 segs

    const bool hasG = (qt == 0) || (qt == 63);
    const int  tlo  = max(0, i0 - 512) >> 6;
    const int  thi  = min(LDIM - 1, i0 + 63 + 512) >> 6;
    const int  cnt  = hasG ? 64 : (thi - tlo + 1);
    const int  t0   = hasG ? 0 : tlo;

    cp16(&Qs[k_row][k_seg * 8], &qb[(size_t)(i0 + k_row) * HD + k_seg * 8]);

    if (!hasG) {
        if (t < 16) {
            int row = t >> 2, seg = t & 3;
            int jr = (row == 0) ? 0 : (row == 1) ? 63 : (row == 2) ? 4032 : 4095;
            *(uint4*)&GsK[row][seg * 8] = *(const uint4*)&kb[(size_t)jr * HD + seg * 8];
        } else if (t < 32) {
            int row = 4 + ((t - 16) >> 2), seg = t & 3;
            uint4 z = {0u, 0u, 0u, 0u};
            *(uint4*)&GsK[row][seg * 8] = z;
        } else if (t < 64) {
            int c = t - 32;
            Vgt[c][0] = vbt[(size_t)c * LDIM + 0];
            Vgt[c][1] = vbt[(size_t)c * LDIM + 63];
            Vgt[c][2] = vbt[(size_t)c * LDIM + 4032];
            Vgt[c][3] = vbt[(size_t)c * LDIM + 4095];
            #pragma unroll
            for (int jj = 4; jj < 12; jj++) Vgt[c][jj] = __float2half(0.f);
        }
    }
    {   // prologue: first K/V tile -> buf 0
        const int j0 = t0 * 64;
        cp16(&Ks[0][k_row][k_seg * 8], &kb[(size_t)(j0 + k_row) * HD + k_seg * 8]);
        cp16(&Vt[0][v_c][v_seg * 8],   &vbt[(size_t)v_c * LDIM + j0 + v_seg * 8]);
        cp_commit();
    }
    cp_wait0();
    __syncthreads();

    // Q A-fragments (2 k-steps x 4 regs), hoisted
    unsigned aq[2][4];
    const int r0 = wr * 16 + g;
    const int r1 = r0 + 8;
    #pragma unroll
    for (int ks = 0; ks < 2; ks++) {
        aq[ks][0] = *(const unsigned*)&Qs[r0][16 * ks + 2 * tg];
        aq[ks][1] = *(const unsigned*)&Qs[r1][16 * ks + 2 * tg];
        aq[ks][2] = *(const unsigned*)&Qs[r0][16 * ks + 2 * tg + 8];
        aq[ks][3] = *(const unsigned*)&Qs[r1][16 * ks + 2 * tg + 8];
    }

    const int ir0 = i0 + r0, ir1 = i0 + r1;
    const bool ig0 = (ir0 == 0) || (ir0 == 63) || (ir0 == 4032) || (ir0 == 4095);
    const bool ig1 = (ir1 == 0) || (ir1 == 63) || (ir1 == 4032) || (ir1 == 4095);

    float oacc[4][4] = {};
    float ls0 = 0.f, ls1 = 0.f;
    int tcur = t0;

    for (int it = 0; it < cnt; it++) {
        const int cur = it & 1;
        const int tcomp = tcur;
        const int j0 = tcomp * 64;

        cp_wait0();
        __syncthreads();
        if (it + 1 < cnt) {
            const int tnext = hasG ? (it + 1) : (tlo + it + 1);
            const int jn = tnext * 64;
            const int nxt = 1 - cur;
            cp16(&Ks[nxt][k_row][k_seg * 8], &kb[(size_t)(jn + k_row) * HD + k_seg * 8]);
            cp16(&Vt[nxt][v_c][v_seg * 8],   &vbt[(size_t)v_c * LDIM + jn + v_seg * 8]);
            cp_commit();
            tcur = tnext;
        }

        // S = Q @ K^T : 4 nb x 2 ks
        float sacc[4][4] = {};
        #pragma unroll
        for (int nb = 0; nb < 4; nb++) {
            int jn = wc * 32 + nb * 8 + g;
            #pragma unroll
            for (int ks = 0; ks < 2; ks++) {
                unsigned bk[2] = {*(const unsigned*)&Ks[cur][jn][16 * ks + 2 * tg],
                                  *(const unsigned*)&Ks[cur][jn][16 * ks + 2 * tg + 8]};
                mma16(sacc[nb], aq[ks], bk);
            }
        }

        // exp2 (+ mask on edge tiles / hasG)
        float p[4][4];
        const bool mtile = hasG || (tcomp == tlo) || (tcomp == thi);
        if (!mtile) {
            #pragma unroll
            for (int nb = 0; nb < 4; nb++) {
                p[nb][0] = exp2f(sacc[nb][0]);
                p[nb][1] = exp2f(sacc[nb][1]);
                p[nb][2] = exp2f(sacc[nb][2]);
                p[nb][3] = exp2f(sacc[nb][3]);
                ls0 += p[nb][0] + p[nb][1];
                ls1 += p[nb][2] + p[nb][3];
            }
        } else {
            #pragma unroll
            for (int nb = 0; nb < 4; nb++) {
                int jb = j0 + wc * 32 + nb * 8 + 2 * tg;
                int jb1 = jb + 1;
                bool jg0 = (jb == 0) || (jb == 63) || (jb == 4032) || (jb == 4095);
                bool jg1 = (jb1 == 0) || (jb1 == 63) || (jb1 == 4032) || (jb1 == 4095);
                int d00 = ir0 - jb, d01 = ir0 - jb1, d10 = ir1 - jb, d11 = ir1 - jb1;
                p[nb][0] = (ig0 || jg0 || (d00 <= 512 && d00 >= -512)) ? exp2f(sacc[nb][0]) : 0.f;
                p[nb][1] = (ig0 || jg1 || (d01 <= 512 && d01 >= -512)) ? exp2f(sacc[nb][1]) : 0.f;
                p[nb][2] = (ig1 || jg0 || (d10 <= 512 && d10 >= -512)) ? exp2f(sacc[nb][2]) : 0.f;
                p[nb][3] = (ig1 || jg1 || (d11 <= 512 && d11 >= -512)) ? exp2f(sacc[nb][3]) : 0.f;
                ls0 += p[nb][0] + p[nb][1];
                ls1 += p[nb][2] + p[nb][3];
            }
        }

        // pack P directly into PV A-fragments (accumulator layout == A layout)
        unsigned ap[2][4];
        #pragma unroll
        for (int ks = 0; ks < 2; ks++) {
            ap[ks][0] = pk2(p[2 * ks][0],     p[2 * ks][1]);
            ap[ks][1] = pk2(p[2 * ks][2],     p[2 * ks][3]);
            ap[ks][2] = pk2(p[2 * ks + 1][0], p[2 * ks + 1][1]);
            ap[ks][3] = pk2(p[2 * ks + 1][2], p[2 * ks + 1][3]);
        }

        // O += P @ V : 2 ks x 4 nb2
        #pragma unroll
        for (int ks = 0; ks < 2; ks++) {
            const int jcol = wc * 32 + 16 * ks + 2 * tg;
            #pragma unroll
            for (int nb2 = 0; nb2 < 4; nb2++) {
                int cn = nb2 * 8 + g;
                unsigned bv[2] = {*(const unsigned*)&Vt[cur][cn][jcol],
                                  *(const unsigned*)&Vt[cur][cn][jcol + 8]};
                mma16(oacc[nb2], ap[ks], bv);
            }
        }
    }

    // Global-token epilogue (non-hasG; wc==0 warps), zero-padded to k=16
    if (!hasG && wc == 0) {
        float sg[4] = {};
        #pragma unroll
        for (int ks = 0; ks < 2; ks++) {
            unsigned bg[2] = {*(const unsigned*)&GsK[g][16 * ks + 2 * tg],
                              *(const unsigned*)&GsK[g][16 * ks + 2 * tg + 8]};
            mma16(sg, aq[ks], bg);
        }
        const bool leadOK  = (tlo > 0);
        const bool trailOK = (thi < 63);
        const int c0i = 2 * tg, c1i = 2 * tg + 1;
        const bool v0 = (c0i < 2) ? leadOK : (c0i < 4 ? trailOK : false);
        const bool v1 = (c1i < 2) ? leadOK : (c1i < 4 ? trailOK : false);
        float pg0 = v0 ? exp2f(sg[0]) : 0.f;
        float pg1 = v1 ? exp2f(sg[1]) : 0.f;
        float pg2 = v0 ? exp2f(sg[2]) : 0.f;
        float pg3 = v1 ? exp2f(sg[3]) : 0.f;
        ls0 += pg0 + pg1;
        ls1 += pg2 + pg3;
        unsigned apg[4] = {pk2(pg0, pg1), pk2(pg2, pg3), 0u, 0u};
        #pragma unroll
        for (int nb2 = 0; nb2 < 4; nb2++) {
            int cn = nb2 * 8 + g;
            unsigned bvg[2] = {*(const unsigned*)&Vgt[cn][2 * tg], 0u};
            mma16(oacc[nb2], apg, bvg);
        }
    }

    // row-sum reduction over tg; combine wc halves via smem
    ls0 += __shfl_xor_sync(~0u, ls0, 1); ls0 += __shfl_xor_sync(~0u, ls0, 2);
    ls1 += __shfl_xor_sync(~0u, ls1, 1); ls1 += __shfl_xor_sync(~0u, ls1, 2);
    if (tg == 0) { Lsm[r0][wc] = ls0; Lsm[r1][wc] = ls1; }
    if (wc == 1) {
        #pragma unroll
        for (int nb2 = 0; nb2 < 4; nb2++) {
            int c0 = nb2 * 8 + 2 * tg;
            Red[r0][c0] = oacc[nb2][0]; Red[r0][c0 + 1] = oacc[nb2][1];
            Red[r1][c0] = oacc[nb2][2]; Red[r1][c0 + 1] = oacc[nb2][3];
        }
    }
    __syncthreads();

    if (wc == 0) {
        float inv0 = 1.f / (Lsm[r0][0] + Lsm[r0][1]);
        float inv1 = 1.f / (Lsm[r1][0] + Lsm[r1][1]);
        const int b = bh >> 3, h = bh & 7;
        #pragma unroll
        for (int nb2 = 0; nb2 < 4; nb2++) {
            int c0 = nb2 * 8 + 2 * tg;
            float o0 = (oacc[nb2][0] + Red[r0][c0])     * inv0;
            float o1 = (oacc[nb2][1] + Red[r0][c0 + 1]) * inv0;
            float o2 = (oacc[nb2][2] + Red[r1][c0])     * inv1;
            float o3 = (oacc[nb2][3] + Red[r1][c0 + 1]) * inv1;
            g_o[((size_t)b * LDIM + ir0) * CDIM + c0 * 8 + h]       = o0;
            g_o[((size_t)b * LDIM + ir0) * CDIM + (c0 + 1) * 8 + h] = o1;
            g_o[((size_t)b * LDIM + ir1) * CDIM + c0 * 8 + h]       = o2;
            g_o[((size_t)b * LDIM + ir1) * CDIM + (c0 + 1) * 8 + h] = o3;
        }
    }
}

// ---------------------------------------------------------------------------
// Kernel 3: out via tf32 mma; cp.async double buffer. (unchanged)
// ---------------------------------------------------------------------------
__global__ void __launch_bounds__(256) out_gemm(const float* __restrict__ w2,
                                                const float* __restrict__ b2,
                                                float* __restrict__ out) {
    __shared__ float WsF[2][32][72];
    __shared__ float OsF[2][64][36];

    const int b  = blockIdx.z;
    const int m0 = blockIdx.x * 64;
    const int n0 = blockIdx.y * 64;
    const int t  = threadIdx.x;
    const int lane = t & 31;
    const int warp = t >> 5;
    const int wr = warp >> 1;
    const int wc = warp & 1;
    const int g  = lane >> 2;
    const int tg = lane & 3;

    const float* ob = g_o + (size_t)b * LDIM * CDIM;
    float acc[4][4] = {};

    const int w_kk = t >> 4, w_n4 = (t & 15) * 4;
    const int w_kk2 = w_kk + 16;
    const int o_mm = t >> 3, o_k4 = (t & 7) * 4;
    const int o_mm2 = o_mm + 32;

    cp16(&WsF[0][w_kk][w_n4],  &w2[(size_t)w_kk  * CDIM + n0 + w_n4]);
    cp16(&WsF[0][w_kk2][w_n4], &w2[(size_t)w_kk2 * CDIM + n0 + w_n4]);
    cp16(&OsF[0][o_mm][o_k4],  &ob[(size_t)(m0 + o_mm)  * CDIM + o_k4]);
    cp16(&OsF[0][o_mm2][o_k4], &ob[(size_t)(m0 + o_mm2) * CDIM + o_k4]);
    cp_commit();

    #pragma unroll
    for (int i = 0; i < 8; i++) {
        const int cur = i & 1;
        cp_wait0();
        __syncthreads();
        if (i < 7) {
            const int nxt = 1 - cur;
            const int kn = (i + 1) * 32;
            cp16(&WsF[nxt][w_kk][w_n4],  &w2[(size_t)(kn + w_kk)  * CDIM + n0 + w_n4]);
            cp16(&WsF[nxt][w_kk2][w_n4], &w2[(size_t)(kn + w_kk2) * CDIM + n0 + w_n4]);
            cp16(&OsF[nxt][o_mm][o_k4],  &ob[(size_t)(m0 + o_mm)  * CDIM + kn + o_k4]);
            cp16(&OsF[nxt][o_mm2][o_k4], &ob[(size_t)(m0 + o_mm2) * CDIM + kn + o_k4]);
            cp_commit();
        }
        unsigned af[4][4];
        #pragma unroll
        for (int ks = 0; ks < 4; ks++) {
            af[ks][0] = f2tf(WsF[cur][ks * 8 + tg][wr * 16 + g]);
            af[ks][1] = f2tf(WsF[cur][ks * 8 + tg][wr * 16 + g + 8]);
            af[ks][2] = f2tf(WsF[cur][ks * 8 + tg + 4][wr * 16 + g]);
            af[ks][3] = f2tf(WsF[cur][ks * 8 + tg + 4][wr * 16 + g + 8]);
        }
        #pragma unroll
        for (int mb = 0; mb < 4; mb++) {
            int mc = wc * 32 + mb * 8 + g;
            #pragma unroll
            for (int ks = 0; ks < 4; ks++) {
                unsigned bf[2] = {f2tf(OsF[cur][mc][ks * 8 + tg]),
                                  f2tf(OsF[cur][mc][ks * 8 + tg + 4])};
                mma8(acc[mb], af[ks], bf);
            }
        }
    }

    const int n_r0 = n0 + wr * 16 + g;
    const int n_r1 = n_r0 + 8;
    const float bias0 = b2[n_r0];
    const float bias1 = b2[n_r1];
    #pragma unroll
    for (int mb = 0; mb < 4; mb++) {
        int mA = m0 + wc * 32 + mb * 8 + 2 * tg;
        float2 v0 = {acc[mb][0] + bias0, acc[mb][1] + bias0};
        float2 v1 = {acc[mb][2] + bias1, acc[mb][3] + bias1};
        *(float2*)&out[((size_t)b * CDIM + n_r0) * LDIM + mA] = v0;
        *(float2*)&out[((size_t)b * CDIM + n_r1) * LDIM + mA] = v1;
    }
}

// ---------------------------------------------------------------------------
extern "C" void kernel_launch(void* const* d_in, const int* in_sizes, int n_in,
                              void* d_out, int out_size) {
    const float* x  = (const float*)d_in[0];
    const float* w1 = (const float*)d_in[1];
    const float* b1 = (const float*)d_in[2];
    const float* w2 = (const float*)d_in[3];
    const float* b2 = (const float*)d_in[4];
    float* out = (float*)d_out;

    qkv_gemm<<<dim3(LDIM / 64, N3C / 64, BSZ), 256>>>(x, w1, b1);
    attn_kernel<<<dim3(LDIM / 64, BSZ * HEADS), 256>>>();
    out_gemm<<<dim3(LDIM / 64, CDIM / 64, BSZ), 256>>>(w2, b2, out);
}

// round 10
// speedup vs baseline: 2.0256x; 1.2841x over previous
#include <cuda_runtime.h>
#include <cuda_fp16.h>
#include <math.h>

#define BSZ   2
#define CDIM  256
#define LDIM  4096
#define HEADS 8
#define HD    32
#define N3C   768

// fp16 scratch
__device__ __half g_xh [BSZ*LDIM*CDIM];   // x^T  [b][L][C]
__device__ __half g_w1t[N3C*CDIM];        // w1^T [768][256]
__device__ __half g_w2t[CDIM*CDIM];       // w2^T [256][256]
__device__ __half g_q[BSZ*HEADS*LDIM*HD]; // [bh][L][32]
__device__ __half g_k[BSZ*HEADS*LDIM*HD]; // [bh][L][32]
__device__ __half g_v[BSZ*HEADS*LDIM*HD]; // [bh][c][L] channel-major
__device__ __half g_o[BSZ*LDIM*CDIM];     // [b][L][C]

// fp16 m16n8k16
__device__ __forceinline__ void mma16(float* c, const unsigned* a, const unsigned* b) {
    asm volatile(
        "mma.sync.aligned.m16n8k16.row.col.f32.f16.f16.f32 "
        "{%0,%1,%2,%3},{%4,%5,%6,%7},{%8,%9},{%0,%1,%2,%3};"
        : "+f"(c[0]), "+f"(c[1]), "+f"(c[2]), "+f"(c[3])
        : "r"(a[0]), "r"(a[1]), "r"(a[2]), "r"(a[3]), "r"(b[0]), "r"(b[1]));
}

__device__ __forceinline__ unsigned pk2(float lo, float hi) {
    unsigned r;
    asm("cvt.rn.f16x2.f32 %0, %1, %2;" : "=r"(r) : "f"(hi), "f"(lo));
    return r;
}
__device__ __forceinline__ unsigned ex2h2(unsigned s) {
    unsigned r;
    asm("ex2.approx.f16x2 %0, %1;" : "=r"(r) : "r"(s));
    return r;
}

__device__ __forceinline__ void cp16(void* s, const void* g) {
    unsigned sa = (unsigned)__cvta_generic_to_shared(s);
    asm volatile("cp.async.cg.shared.global [%0], [%1], 16;" :: "r"(sa), "l"(g));
}
__device__ __forceinline__ void cp_commit() { asm volatile("cp.async.commit_group;"); }
__device__ __forceinline__ void cp_wait0()  { asm volatile("cp.async.wait_group 0;"); }

// ---------------------------------------------------------------------------
// Transpose + f32->f16 convert: dst[c][r] = (half)src[r][c]
// block (32,8), grid (cols/32, rows/32, batch)
// ---------------------------------------------------------------------------
__global__ void transpose_f2h(const float* __restrict__ src, __half* __restrict__ dst,
                              int rows, int cols) {
    __shared__ float tile[32][33];
    const int bz = blockIdx.z;
    src += (size_t)bz * rows * cols;
    dst += (size_t)bz * rows * cols;
    const int c0 = blockIdx.x * 32, r0 = blockIdx.y * 32;
    const int tx = threadIdx.x, ty = threadIdx.y;
    #pragma unroll
    for (int i = 0; i < 4; i++)
        tile[ty + 8 * i][tx] = src[(size_t)(r0 + ty + 8 * i) * cols + c0 + tx];
    __syncthreads();
    #pragma unroll
    for (int i = 0; i < 4; i++)
        dst[(size_t)(c0 + ty + 8 * i) * rows + r0 + tx] = __float2half_rn(tile[tx][ty + 8 * i]);
}

// ---------------------------------------------------------------------------
// Kernel 1: qkv = x^T @ w1 + b1 via fp16 m16n8k16 (operand-swapped).
// A = w1t [n][k], B = xh [m][k]; cp.async double buffer.
// ---------------------------------------------------------------------------
__global__ void __launch_bounds__(256) qkv_gemm(const float* __restrict__ b1) {
    __shared__ __half Wt[2][64][40];
    __shared__ __half Xt[2][64][40];

    const int b  = blockIdx.z;
    const int m0 = blockIdx.x * 64;
    const int n0 = blockIdx.y * 64;
    const int t  = threadIdx.x;
    const int lane = t & 31;
    const int warp = t >> 5;
    const int wr = warp >> 1;
    const int wc = warp & 1;
    const int g  = lane >> 2;
    const int tg = lane & 3;

    const __half* xb = g_xh + (size_t)b * LDIM * CDIM;
    float acc[4][4] = {};

    const int s_row = t >> 2, s_seg = (t & 3) * 8;

    cp16(&Wt[0][s_row][s_seg], &g_w1t[(size_t)(n0 + s_row) * CDIM + s_seg]);
    cp16(&Xt[0][s_row][s_seg], &xb[(size_t)(m0 + s_row) * CDIM + s_seg]);
    cp_commit();

    #pragma unroll
    for (int i = 0; i < 8; i++) {
        const int cur = i & 1;
        cp_wait0();
        __syncthreads();
        if (i < 7) {
            const int nxt = 1 - cur;
            const int kn = (i + 1) * 32;
            cp16(&Wt[nxt][s_row][s_seg], &g_w1t[(size_t)(n0 + s_row) * CDIM + kn + s_seg]);
            cp16(&Xt[nxt][s_row][s_seg], &xb[(size_t)(m0 + s_row) * CDIM + kn + s_seg]);
            cp_commit();
        }
        #pragma unroll
        for (int ks = 0; ks < 2; ks++) {
            unsigned af[4];
            af[0] = *(const unsigned*)&Wt[cur][wr * 16 + g][16 * ks + 2 * tg];
            af[1] = *(const unsigned*)&Wt[cur][wr * 16 + g + 8][16 * ks + 2 * tg];
            af[2] = *(const unsigned*)&Wt[cur][wr * 16 + g][16 * ks + 2 * tg + 8];
            af[3] = *(const unsigned*)&Wt[cur][wr * 16 + g + 8][16 * ks + 2 * tg + 8];
            #pragma unroll
            for (int mb = 0; mb < 4; mb++) {
                int mc = wc * 32 + mb * 8 + g;
                unsigned bf[2] = {*(const unsigned*)&Xt[cur][mc][16 * ks + 2 * tg],
                                  *(const unsigned*)&Xt[cur][mc][16 * ks + 2 * tg + 8]};
                mma16(acc[mb], af, bf);
            }
        }
    }

    const float q_scale = 0.1767766952966368811f * 1.4426950408889634f;
    const int n_r0 = n0 + wr * 16 + g;
    const int n_r1 = n_r0 + 8;
    const int k3_0 = n_r0 % 3, h_0 = (n_r0 / 3) & 7, c_0 = n_r0 / 24;
    const int k3_1 = n_r1 % 3, h_1 = (n_r1 / 3) & 7, c_1 = n_r1 / 24;
    const float bias0 = b1[n_r0], bias1 = b1[n_r1];
    const float sc0 = (k3_0 == 0) ? q_scale : 1.f;
    const float sc1 = (k3_1 == 0) ? q_scale : 1.f;
    const int bh0 = b * HEADS + h_0, bh1 = b * HEADS + h_1;

    #pragma unroll
    for (int mb = 0; mb < 4; mb++) {
        int mA = m0 + wc * 32 + mb * 8 + 2 * tg;
        float v00 = (acc[mb][0] + bias0) * sc0, v01 = (acc[mb][1] + bias0) * sc0;
        float v10 = (acc[mb][2] + bias1) * sc1, v11 = (acc[mb][3] + bias1) * sc1;
        if (k3_0 == 2) {
            *(__half2*)&g_v[((size_t)bh0 * HD + c_0) * LDIM + mA] = __floats2half2_rn(v00, v01);
        } else {
            __half* d = (k3_0 == 0) ? g_q : g_k;
            d[((size_t)bh0 * LDIM + mA)     * HD + c_0] = __float2half_rn(v00);
            d[((size_t)bh0 * LDIM + mA + 1) * HD + c_0] = __float2half_rn(v01);
        }
        if (k3_1 == 2) {
            *(__half2*)&g_v[((size_t)bh1 * HD + c_1) * LDIM + mA] = __floats2half2_rn(v10, v11);
        } else {
            __half* d = (k3_1 == 0) ? g_q : g_k;
            d[((size_t)bh1 * LDIM + mA)     * HD + c_1] = __float2half_rn(v10);
            d[((size_t)bh1 * LDIM + mA + 1) * HD + c_1] = __float2half_rn(v11);
        }
    }
}

// ---------------------------------------------------------------------------
// Kernel 2: banded attention, fp16 m16n8k16. S masked in fp32, packed to
// f16x2, ex2.approx.f16x2 -> PV A-frags. Row sums via ones-column MMA.
// ---------------------------------------------------------------------------
__global__ void __launch_bounds__(256) attn_kernel() {
    __shared__ __half Qs[64][40];
    __shared__ __half Ks[2][64][40];
    __shared__ __half Vt[2][32][72];
    __shared__ __half GsK[8][40];
    __shared__ __half Vgt[32][12];
    __shared__ float  Red[64][33];
    __shared__ float  Lsm[64][2];

    const int qt = blockIdx.x;
    const int bh = blockIdx.y;
    const int i0 = qt * 64;
    const int t  = threadIdx.x;
    const int lane = t & 31;
    const int warp = t >> 5;
    const int wr = warp >> 1;
    const int wc = warp & 1;
    const int g  = lane >> 2;
    const int tg = lane & 3;

    const __half* qb  = g_q + (size_t)bh * LDIM * HD;
    const __half* kb  = g_k + (size_t)bh * LDIM * HD;
    const __half* vbt = g_v + (size_t)bh * HD * LDIM;

    const int k_row = t >> 2, k_seg = t & 3;
    const int v_c   = t >> 3, v_seg = t & 7;

    const bool hasG = (qt == 0) || (qt == 63);
    const int  tlo  = max(0, i0 - 512) >> 6;
    const int  thi  = min(LDIM - 1, i0 + 63 + 512) >> 6;
    const int  cnt  = hasG ? 64 : (thi - tlo + 1);
    const int  t0   = hasG ? 0 : tlo;

    cp16(&Qs[k_row][k_seg * 8], &qb[(size_t)(i0 + k_row) * HD + k_seg * 8]);

    if (!hasG) {
        if (t < 16) {
            int row = t >> 2, seg = t & 3;
            int jr = (row == 0) ? 0 : (row == 1) ? 63 : (row == 2) ? 4032 : 4095;
            *(uint4*)&GsK[row][seg * 8] = *(const uint4*)&kb[(size_t)jr * HD + seg * 8];
        } else if (t < 32) {
            int row = 4 + ((t - 16) >> 2), seg = t & 3;
            uint4 z = {0u, 0u, 0u, 0u};
            *(uint4*)&GsK[row][seg * 8] = z;
        } else if (t < 64) {
            int c = t - 32;
            Vgt[c][0] = vbt[(size_t)c * LDIM + 0];
            Vgt[c][1] = vbt[(size_t)c * LDIM + 63];
            Vgt[c][2] = vbt[(size_t)c * LDIM + 4032];
            Vgt[c][3] = vbt[(size_t)c * LDIM + 4095];
            #pragma unroll
            for (int jj = 4; jj < 12; jj++) Vgt[c][jj] = __float2half(0.f);
        }
    }
    {
        const int j0 = t0 * 64;
        cp16(&Ks[0][k_row][k_seg * 8], &kb[(size_t)(j0 + k_row) * HD + k_seg * 8]);
        cp16(&Vt[0][v_c][v_seg * 8],   &vbt[(size_t)v_c * LDIM + j0 + v_seg * 8]);
        cp_commit();
    }
    cp_wait0();
    __syncthreads();

    unsigned aq[2][4];
    const int r0 = wr * 16 + g;
    const int r1 = r0 + 8;
    #pragma unroll
    for (int ks = 0; ks < 2; ks++) {
        aq[ks][0] = *(const unsigned*)&Qs[r0][16 * ks + 2 * tg];
        aq[ks][1] = *(const unsigned*)&Qs[r1][16 * ks + 2 * tg];
        aq[ks][2] = *(const unsigned*)&Qs[r0][16 * ks + 2 * tg + 8];
        aq[ks][3] = *(const unsigned*)&Qs[r1][16 * ks + 2 * tg + 8];
    }

    const int ir0 = i0 + r0, ir1 = i0 + r1;
    const bool ig0 = (ir0 == 0) || (ir0 == 63) || (ir0 == 4032) || (ir0 == 4095);
    const bool ig1 = (ir1 == 0) || (ir1 == 63) || (ir1 == 4032) || (ir1 == 4095);

    const unsigned ones2 = 0x3C003C00u;       // half2 {1,1}
    const unsigned onesB[2] = {ones2, ones2};

    float oacc[4][4] = {};
    float lacc[4] = {};
    int tcur = t0;

    for (int it = 0; it < cnt; it++) {
        const int cur = it & 1;
        const int tcomp = tcur;
        const int j0 = tcomp * 64;

        cp_wait0();
        __syncthreads();
        if (it + 1 < cnt) {
            const int tnext = hasG ? (it + 1) : (tlo + it + 1);
            const int jn = tnext * 64;
            const int nxt = 1 - cur;
            cp16(&Ks[nxt][k_row][k_seg * 8], &kb[(size_t)(jn + k_row) * HD + k_seg * 8]);
            cp16(&Vt[nxt][v_c][v_seg * 8],   &vbt[(size_t)v_c * LDIM + jn + v_seg * 8]);
            cp_commit();
            tcur = tnext;
        }

        // S = Q @ K^T
        float sacc[4][4] = {};
        #pragma unroll
        for (int nb = 0; nb < 4; nb++) {
            int jn = wc * 32 + nb * 8 + g;
            #pragma unroll
            for (int ks = 0; ks < 2; ks++) {
                unsigned bk[2] = {*(const unsigned*)&Ks[cur][jn][16 * ks + 2 * tg],
                                  *(const unsigned*)&Ks[cur][jn][16 * ks + 2 * tg + 8]};
                mma16(sacc[nb], aq[ks], bk);
            }
        }

        // mask (edge tiles / hasG only): invalid -> -1e30 (-> -inf half -> exp2=0)
        if (hasG || (tcomp == tlo) || (tcomp == thi)) {
            #pragma unroll
            for (int nb = 0; nb < 4; nb++) {
                int jb = j0 + wc * 32 + nb * 8 + 2 * tg;
                int jb1 = jb + 1;
                bool jg0 = (jb == 0) || (jb == 63) || (jb == 4032) || (jb == 4095);
                bool jg1 = (jb1 == 0) || (jb1 == 63) || (jb1 == 4032) || (jb1 == 4095);
                int d00 = ir0 - jb, d01 = ir0 - jb1, d10 = ir1 - jb, d11 = ir1 - jb1;
                if (!(ig0 || jg0 || (d00 <= 512 && d00 >= -512))) sacc[nb][0] = -1e30f;
                if (!(ig0 || jg1 || (d01 <= 512 && d01 >= -512))) sacc[nb][1] = -1e30f;
                if (!(ig1 || jg0 || (d10 <= 512 && d10 >= -512))) sacc[nb][2] = -1e30f;
                if (!(ig1 || jg1 || (d11 <= 512 && d11 >= -512))) sacc[nb][3] = -1e30f;
            }
        }

        // P = exp2(S) packed directly as PV A-frags; row sums via ones MMA
        #pragma unroll
        for (int ks = 0; ks < 2; ks++) {
            unsigned ap[4];
            ap[0] = ex2h2(pk2(sacc[2 * ks][0],     sacc[2 * ks][1]));
            ap[1] = ex2h2(pk2(sacc[2 * ks][2],     sacc[2 * ks][3]));
            ap[2] = ex2h2(pk2(sacc[2 * ks + 1][0], sacc[2 * ks + 1][1]));
            ap[3] = ex2h2(pk2(sacc[2 * ks + 1][2], sacc[2 * ks + 1][3]));
            mma16(lacc, ap, onesB);
            const int jcol = wc * 32 + 16 * ks + 2 * tg;
            #pragma unroll
            for (int nb2 = 0; nb2 < 4; nb2++) {
                int cn = nb2 * 8 + g;
                unsigned bv[2] = {*(const unsigned*)&Vt[cur][cn][jcol],
                                  *(const unsigned*)&Vt[cur][cn][jcol + 8]};
                mma16(oacc[nb2], ap, bv);
            }
        }
    }

    // Global-token epilogue (non-hasG; wc==0 warps), zero-padded to k=16
    if (!hasG && wc == 0) {
        float sg[4] = {};
        #pragma unroll
        for (int ks = 0; ks < 2; ks++) {
            unsigned bg[2] = {*(const unsigned*)&GsK[g][16 * ks + 2 * tg],
                              *(const unsigned*)&GsK[g][16 * ks + 2 * tg + 8]};
            mma16(sg, aq[ks], bg);
        }
        const bool leadOK  = (tlo > 0);
        const bool trailOK = (thi < 63);
        const int c0i = 2 * tg, c1i = 2 * tg + 1;
        const bool v0 = (c0i < 2) ? leadOK : (c0i < 4 ? trailOK : false);
        const bool v1 = (c1i < 2) ? leadOK : (c1i < 4 ? trailOK : false);
        if (!v0) { sg[0] = -1e30f; sg[2] = -1e30f; }
        if (!v1) { sg[1] = -1e30f; sg[3] = -1e30f; }
        unsigned apg[4] = {ex2h2(pk2(sg[0], sg[1])), ex2h2(pk2(sg[2], sg[3])), 0u, 0u};
        mma16(lacc, apg, onesB);
        #pragma unroll
        for (int nb2 = 0; nb2 < 4; nb2++) {
            int cn = nb2 * 8 + g;
            unsigned bvg[2] = {*(const unsigned*)&Vgt[cn][2 * tg], 0u};
            mma16(oacc[nb2], apg, bvg);
        }
    }

    // lacc[0] = rowsum(r0), lacc[2] = rowsum(r1) for this warp's key half
    if (tg == 0) { Lsm[r0][wc] = lacc[0]; Lsm[r1][wc] = lacc[2]; }
    if (wc == 1) {
        #pragma unroll
        for (int nb2 = 0; nb2 < 4; nb2++) {
            int c0 = nb2 * 8 + 2 * tg;
            Red[r0][c0] = oacc[nb2][0]; Red[r0][c0 + 1] = oacc[nb2][1];
            Red[r1][c0] = oacc[nb2][2]; Red[r1][c0 + 1] = oacc[nb2][3];
        }
    }
    __syncthreads();

    if (wc == 0) {
        float inv0 = 1.f / (Lsm[r0][0] + Lsm[r0][1]);
        float inv1 = 1.f / (Lsm[r1][0] + Lsm[r1][1]);
        const int b = bh >> 3, h = bh & 7;
        #pragma unroll
        for (int nb2 = 0; nb2 < 4; nb2++) {
            int c0 = nb2 * 8 + 2 * tg;
            float o0 = (oacc[nb2][0] + Red[r0][c0])     * inv0;
            float o1 = (oacc[nb2][1] + Red[r0][c0 + 1]) * inv0;
            float o2 = (oacc[nb2][2] + Red[r1][c0])     * inv1;
            float o3 = (oacc[nb2][3] + Red[r1][c0 + 1]) * inv1;
            g_o[((size_t)b * LDIM + ir0) * CDIM + c0 * 8 + h]       = __float2half_rn(o0);
            g_o[((size_t)b * LDIM + ir0) * CDIM + (c0 + 1) * 8 + h] = __float2half_rn(o1);
            g_o[((size_t)b * LDIM + ir1) * CDIM + c0 * 8 + h]       = __float2half_rn(o2);
            g_o[((size_t)b * LDIM + ir1) * CDIM + (c0 + 1) * 8 + h] = __float2half_rn(o3);
        }
    }
}

// ---------------------------------------------------------------------------
// Kernel 3: out = o @ w2 + b2 via fp16 m16n8k16 (operand-swapped).
// A = w2t [n][k], B = g_o [m][k].
// ---------------------------------------------------------------------------
__global__ void __launch_bounds__(256) out_gemm(const float* __restrict__ b2,
                                               float* __restrict__ out) {
    __shared__ __half Wt[2][64][40];
    __shared__ __half Os[2][64][40];

    const int b  = blockIdx.z;
    const int m0 = blockIdx.x * 64;
    const int n0 = blockIdx.y * 64;
    const int t  = threadIdx.x;
    const int lane = t & 31;
    const int warp = t >> 5;
    const int wr = warp >> 1;
    const int wc = warp & 1;
    const int g  = lane >> 2;
    const int tg = lane & 3;

    const __half* ob = g_o + (size_t)b * LDIM * CDIM;
    float acc[4][4] = {};

    const int s_row = t >> 2, s_seg = (t & 3) * 8;

    cp16(&Wt[0][s_row][s_seg], &g_w2t[(size_t)(n0 + s_row) * CDIM + s_seg]);
    cp16(&Os[0][s_row][s_seg], &ob[(size_t)(m0 + s_row) * CDIM + s_seg]);
    cp_commit();

    #pragma unroll
    for (int i = 0; i < 8; i++) {
        const int cur = i & 1;
        cp_wait0();
        __syncthreads();
        if (i < 7) {
            const int nxt = 1 - cur;
            const int kn = (i + 1) * 32;
            cp16(&Wt[nxt][s_row][s_seg], &g_w2t[(size_t)(n0 + s_row) * CDIM + kn + s_seg]);
            cp16(&Os[nxt][s_row][s_seg], &ob[(size_t)(m0 + s_row) * CDIM + kn + s_seg]);
            cp_commit();
        }
        #pragma unroll
        for (int ks = 0; ks < 2; ks++) {
            unsigned af[4];
            af[0] = *(const unsigned*)&Wt[cur][wr * 16 + g][16 * ks + 2 * tg];
            af[1] = *(const unsigned*)&Wt[cur][wr * 16 + g + 8][16 * ks + 2 * tg];
            af[2] = *(const unsigned*)&Wt[cur][wr * 16 + g][16 * ks + 2 * tg + 8];
            af[3] = *(const unsigned*)&Wt[cur][wr * 16 + g + 8][16 * ks + 2 * tg + 8];
            #pragma unroll
            for (int mb = 0; mb < 4; mb++) {
                int mc = wc * 32 + mb * 8 + g;
                unsigned bf[2] = {*(const unsigned*)&Os[cur][mc][16 * ks + 2 * tg],
                                  *(const unsigned*)&Os[cur][mc][16 * ks + 2 * tg + 8]};
                mma16(acc[mb], af, bf);
            }
        }
    }

    const int n_r0 = n0 + wr * 16 + g;
    const int n_r1 = n_r0 + 8;
    const float bias0 = b2[n_r0];
    const float bias1 = b2[n_r1];
    #pragma unroll
    for (int mb = 0; mb < 4; mb++) {
        int mA = m0 + wc * 32 + mb * 8 + 2 * tg;
        float2 v0 = {acc[mb][0] + bias0, acc[mb][1] + bias0};
        float2 v1 = {acc[mb][2] + bias1, acc[mb][3] + bias1};
        *(float2*)&out[((size_t)b * CDIM + n_r0) * LDIM + mA] = v0;
        *(float2*)&out[((size_t)b * CDIM + n_r1) * LDIM + mA] = v1;
    }
}

// ---------------------------------------------------------------------------
extern "C" void kernel_launch(void* const* d_in, const int* in_sizes, int n_in,
                              void* d_out, int out_size) {
    const float* x  = (const float*)d_in[0];
    const float* w1 = (const float*)d_in[1];
    const float* b1 = (const float*)d_in[2];
    const float* w2 = (const float*)d_in[3];
    const float* b2 = (const float*)d_in[4];
    float* out = (float*)d_out;

    __half *xh, *w1t, *w2t;
    cudaGetSymbolAddress((void**)&xh,  g_xh);
    cudaGetSymbolAddress((void**)&w1t, g_w1t);
    cudaGetSymbolAddress((void**)&w2t, g_w2t);

    // x [B][C][L] -> xh [B][L][C];  w1 [C][3C] -> w1t [3C][C];  w2 [C][C] -> w2t
    transpose_f2h<<<dim3(LDIM / 32, CDIM / 32, BSZ), dim3(32, 8)>>>(x, xh, CDIM, LDIM);
    transpose_f2h<<<dim3(N3C / 32, CDIM / 32, 1),  dim3(32, 8)>>>(w1, w1t, CDIM, N3C);
    transpose_f2h<<<dim3(CDIM / 32, CDIM / 32, 1), dim3(32, 8)>>>(w2, w2t, CDIM, CDIM);

    qkv_gemm<<<dim3(LDIM / 64, N3C / 64, BSZ), 256>>>(b1);
    attn_kernel<<<dim3(LDIM / 64, BSZ * HEADS), 256>>>();
    out_gemm<<<dim3(LDIM / 64, CDIM / 64, BSZ), 256>>>(b2, out);
}